// round 1
// baseline (speedup 1.0000x reference)
#include <cuda_runtime.h>
#include <math.h>

#define B_DIM 2
#define T_SEQ 2048
#define C_DIM 1024
#define H_DIM 16
#define D_HEAD 64
#define M_ROWS (B_DIM * T_SEQ)       // 4096
#define QKV_COLS (3 * C_DIM)         // 3072

// Scratch (allocation-free rule: __device__ globals)
__device__ float g_qkv[(size_t)M_ROWS * QKV_COLS];  // (B,T,3,H,D) flattened row-major
__device__ float g_y[(size_t)M_ROWS * C_DIM];       // attention output (B,T,C)

// ---------------------------------------------------------------------------
// GEMM NT: C[M,N] = A[M,K] * B[N,K]^T   (both row-major, K contiguous)
// 128x128 block tile, BK=8, 256 threads, 8x8 per thread (split 2x2 of 4x4).
// M,N multiples of 128; K multiple of 8.
// ---------------------------------------------------------------------------
__global__ void __launch_bounds__(256) gemm_nt_kernel(
    const float* __restrict__ A, const float* __restrict__ B,
    float* __restrict__ C, int M, int N, int K)
{
    __shared__ float As[8][128];
    __shared__ float Bs[8][128];

    const int bm = blockIdx.y * 128;
    const int bn = blockIdx.x * 128;
    const int tid = threadIdx.x;
    const int ty = tid / 16;         // 0..15
    const int tx = tid % 16;         // 0..15
    const int lr = tid >> 1;         // 0..127
    const int lc = (tid & 1) * 4;    // 0 or 4

    const float* Ap = A + (size_t)(bm + lr) * K + lc;
    const float* Bp = B + (size_t)(bn + lr) * K + lc;

    float acc[2][2][4][4];
#pragma unroll
    for (int rh = 0; rh < 2; rh++)
#pragma unroll
        for (int ch = 0; ch < 2; ch++)
#pragma unroll
            for (int i = 0; i < 4; i++)
#pragma unroll
                for (int j = 0; j < 4; j++) acc[rh][ch][i][j] = 0.f;

    for (int k0 = 0; k0 < K; k0 += 8) {
        float4 av = *(const float4*)(Ap + k0);
        float4 bv = *(const float4*)(Bp + k0);
        As[lc + 0][lr] = av.x; As[lc + 1][lr] = av.y;
        As[lc + 2][lr] = av.z; As[lc + 3][lr] = av.w;
        Bs[lc + 0][lr] = bv.x; Bs[lc + 1][lr] = bv.y;
        Bs[lc + 2][lr] = bv.z; Bs[lc + 3][lr] = bv.w;
        __syncthreads();

#pragma unroll
        for (int k = 0; k < 8; ++k) {
            float4 a0 = *(const float4*)&As[k][ty * 4];
            float4 a1 = *(const float4*)&As[k][64 + ty * 4];
            float4 b0 = *(const float4*)&Bs[k][tx * 4];
            float4 b1 = *(const float4*)&Bs[k][64 + tx * 4];
            float ar[2][4] = {{a0.x, a0.y, a0.z, a0.w}, {a1.x, a1.y, a1.z, a1.w}};
            float br[2][4] = {{b0.x, b0.y, b0.z, b0.w}, {b1.x, b1.y, b1.z, b1.w}};
#pragma unroll
            for (int rh = 0; rh < 2; rh++)
#pragma unroll
                for (int ch = 0; ch < 2; ch++)
#pragma unroll
                    for (int i = 0; i < 4; i++)
#pragma unroll
                        for (int j = 0; j < 4; j++)
                            acc[rh][ch][i][j] = fmaf(ar[rh][i], br[ch][j], acc[rh][ch][i][j]);
        }
        __syncthreads();
    }

#pragma unroll
    for (int rh = 0; rh < 2; rh++)
#pragma unroll
        for (int i = 0; i < 4; i++) {
            int row = bm + rh * 64 + ty * 4 + i;
#pragma unroll
            for (int ch = 0; ch < 2; ch++) {
                float4 o = make_float4(acc[rh][ch][i][0], acc[rh][ch][i][1],
                                       acc[rh][ch][i][2], acc[rh][ch][i][3]);
                *(float4*)(C + (size_t)row * N + bn + ch * 64 + tx * 4) = o;
            }
        }
}

// ---------------------------------------------------------------------------
// RoPE in-place on q and k thirds of qkv (B,T,3,H,D) layout.
// out[i]    =  x[i]*cos + x[i+32]*sin
// out[i+32] = -x[i]*sin + x[i+32]*cos
// ---------------------------------------------------------------------------
__global__ void rope_kernel(float* __restrict__ qkv)
{
    int idx = blockIdx.x * blockDim.x + threadIdx.x;
    // total = B*T*H*32 = 2^21
    int i = idx & 31;
    int h = (idx >> 5) & 15;
    int t = (idx >> 9) & 2047;
    int b = idx >> 20;

    // match reference f32 computation: inv_freq = 1/10000^(2i/64)
    float p = powf(10000.0f, (float)(2 * i) * (1.0f / 64.0f));
    float ang = (float)t * (1.0f / p);
    float s, c;
    sincosf(ang, &s, &c);

    size_t base = ((size_t)(b * T_SEQ + t)) * QKV_COLS + h * D_HEAD;
    // q
    float q1 = qkv[base + i], q2 = qkv[base + i + 32];
    qkv[base + i]      =  q1 * c + q2 * s;
    qkv[base + i + 32] = -q1 * s + q2 * c;
    // k
    base += C_DIM;
    float k1 = qkv[base + i], k2 = qkv[base + i + 32];
    qkv[base + i]      =  k1 * c + k2 * s;
    qkv[base + i + 32] = -k1 * s + k2 * c;
}

// ---------------------------------------------------------------------------
// fp32 flash attention, causal. 1 thread = 1 query row; 128 queries/block.
// K/V streamed through smem in 16-key tiles. Online softmax.
// grid = (T/128, B*H)
// ---------------------------------------------------------------------------
__global__ void __launch_bounds__(128) flash_kernel(
    const float* __restrict__ qkv, float* __restrict__ y)
{
    __shared__ float4 Ks[16 * 16];  // 16 keys x 64 dims
    __shared__ float4 Vs[16 * 16];

    const int tid = threadIdx.x;
    const int qtile = blockIdx.x;
    const int bh = blockIdx.y;
    const int b = bh >> 4;
    const int h = bh & 15;
    const int qpos = qtile * 128 + tid;

    const float* qptr = qkv + ((size_t)(b * T_SEQ + qpos)) * QKV_COLS + h * D_HEAD;
    float q[64];
#pragma unroll
    for (int dd = 0; dd < 16; ++dd) {
        float4 v = *(const float4*)(qptr + dd * 4);
        q[4 * dd + 0] = v.x * 0.125f;  // fold scale = 1/sqrt(64)
        q[4 * dd + 1] = v.y * 0.125f;
        q[4 * dd + 2] = v.z * 0.125f;
        q[4 * dd + 3] = v.w * 0.125f;
    }

    float m = -1e30f, l = 0.f;
    float acc[64];
#pragma unroll
    for (int d = 0; d < 64; ++d) acc[d] = 0.f;

    const int ntiles = (qtile + 1) * 8;  // keys 0 .. qtile*128+127 in tiles of 16
    const int lrow = tid >> 3;           // 0..15
    const int lcol = (tid & 7) * 8;      // 0,8,..,56
    const float* kbaseptr = qkv + ((size_t)(b * T_SEQ)) * QKV_COLS + C_DIM + h * D_HEAD + lcol;
    const float* vbaseptr = kbaseptr + C_DIM;

    for (int kt = 0; kt < ntiles; ++kt) {
        const int kbase = kt * 16;
        {
            const float* kp = kbaseptr + (size_t)(kbase + lrow) * QKV_COLS;
            const float* vp = vbaseptr + (size_t)(kbase + lrow) * QKV_COLS;
            float4 k0 = *(const float4*)kp;
            float4 k1 = *(const float4*)(kp + 4);
            float4 v0 = *(const float4*)vp;
            float4 v1 = *(const float4*)(vp + 4);
            int so = lrow * 16 + (lcol >> 2);
            Ks[so] = k0; Ks[so + 1] = k1;
            Vs[so] = v0; Vs[so + 1] = v1;
        }
        __syncthreads();

        if (kbase <= qpos) {
            const bool full = (kbase + 15 <= qpos);
            float s[16];
#pragma unroll
            for (int c = 0; c < 16; ++c) {
                float d0 = 0.f, d1 = 0.f, d2 = 0.f, d3 = 0.f;
#pragma unroll
                for (int dd = 0; dd < 16; ++dd) {
                    float4 kv = Ks[c * 16 + dd];
                    d0 = fmaf(q[4 * dd + 0], kv.x, d0);
                    d1 = fmaf(q[4 * dd + 1], kv.y, d1);
                    d2 = fmaf(q[4 * dd + 2], kv.z, d2);
                    d3 = fmaf(q[4 * dd + 3], kv.w, d3);
                }
                float sc = (d0 + d1) + (d2 + d3);
                s[c] = (full || (kbase + c <= qpos)) ? sc : -1e30f;
            }
            float tm = s[0];
#pragma unroll
            for (int c = 1; c < 16; ++c) tm = fmaxf(tm, s[c]);
            float mnew = fmaxf(m, tm);
            float corr = __expf(m - mnew);
            l *= corr;
#pragma unroll
            for (int d = 0; d < 64; ++d) acc[d] *= corr;
#pragma unroll
            for (int c = 0; c < 16; ++c) {
                float pr = __expf(s[c] - mnew);
                l += pr;
#pragma unroll
                for (int dd = 0; dd < 16; ++dd) {
                    float4 vv = Vs[c * 16 + dd];
                    acc[4 * dd + 0] = fmaf(pr, vv.x, acc[4 * dd + 0]);
                    acc[4 * dd + 1] = fmaf(pr, vv.y, acc[4 * dd + 1]);
                    acc[4 * dd + 2] = fmaf(pr, vv.z, acc[4 * dd + 2]);
                    acc[4 * dd + 3] = fmaf(pr, vv.w, acc[4 * dd + 3]);
                }
            }
            m = mnew;
        }
        __syncthreads();
    }

    const float invl = 1.0f / l;
    float* yp = y + ((size_t)(b * T_SEQ + qpos)) * C_DIM + h * D_HEAD;
#pragma unroll
    for (int dd = 0; dd < 16; ++dd) {
        float4 o = make_float4(acc[4 * dd + 0] * invl, acc[4 * dd + 1] * invl,
                               acc[4 * dd + 2] * invl, acc[4 * dd + 3] * invl);
        *(float4*)(yp + 4 * dd) = o;
    }
}

// ---------------------------------------------------------------------------
extern "C" void kernel_launch(void* const* d_in, const int* in_sizes, int n_in,
                              void* d_out, int out_size)
{
    const float* x      = (const float*)d_in[0];  // (B,T,C)
    const float* w_attn = (const float*)d_in[1];  // (3C,C)
    const float* w_proj = (const float*)d_in[2];  // (C,C)
    float* out = (float*)d_out;                   // (B,T,C)

    float* qkv = nullptr;
    float* y = nullptr;
    cudaGetSymbolAddress((void**)&qkv, g_qkv);
    cudaGetSymbolAddress((void**)&y, g_y);

    // 1) qkv = x @ w_attn^T   (M=4096, N=3072, K=1024)
    {
        dim3 grid(QKV_COLS / 128, M_ROWS / 128);
        gemm_nt_kernel<<<grid, 256>>>(x, w_attn, qkv, M_ROWS, QKV_COLS, C_DIM);
    }
    // 2) RoPE in-place on q,k
    {
        int total = B_DIM * T_SEQ * H_DIM * 32;  // 2^21
        rope_kernel<<<total / 256, 256>>>(qkv);
    }
    // 3) causal flash attention -> y (B,T,C)
    {
        dim3 grid(T_SEQ / 128, B_DIM * H_DIM);
        flash_kernel<<<grid, 128>>>(qkv, y);
    }
    // 4) out = y @ w_proj^T   (M=4096, N=1024, K=1024)
    {
        dim3 grid(C_DIM / 128, M_ROWS / 128);
        gemm_nt_kernel<<<grid, 256>>>(y, w_proj, out, M_ROWS, C_DIM, C_DIM);
    }
}

// round 3
// speedup vs baseline: 1.3262x; 1.3262x over previous
#include <cuda_runtime.h>
#include <cuda_bf16.h>
#include <cstdint>
#include <math.h>

#define B_DIM 2
#define T_SEQ 2048
#define C_DIM 1024
#define H_DIM 16
#define D_HEAD 64
#define M_ROWS (B_DIM * T_SEQ)       // 4096
#define QKV_COLS (3 * C_DIM)         // 3072

// ---------------------------------------------------------------------------
// Scratch (allocation-free rule: __device__ globals)
// ---------------------------------------------------------------------------
__device__ float g_qkv[(size_t)M_ROWS * QKV_COLS];   // (B,T,3,H,D)
__device__ float g_y[(size_t)M_ROWS * C_DIM];        // attention output

__device__ __nv_bfloat16 g_xhi[(size_t)M_ROWS * C_DIM];
__device__ __nv_bfloat16 g_xlo[(size_t)M_ROWS * C_DIM];
__device__ __nv_bfloat16 g_wahi[(size_t)QKV_COLS * C_DIM];
__device__ __nv_bfloat16 g_walo[(size_t)QKV_COLS * C_DIM];
__device__ __nv_bfloat16 g_wphi[(size_t)C_DIM * C_DIM];
__device__ __nv_bfloat16 g_wplo[(size_t)C_DIM * C_DIM];
__device__ __nv_bfloat16 g_yhi[(size_t)M_ROWS * C_DIM];
__device__ __nv_bfloat16 g_ylo[(size_t)M_ROWS * C_DIM];

// ---------------------------------------------------------------------------
// helpers
// ---------------------------------------------------------------------------
__device__ __forceinline__ uint32_t smem_to_u32(const void* smem_ptr) {
    uint32_t addr;
    asm("{ .reg .u64 tmp; cvta.to.shared.u64 tmp, %1; cvt.u32.u64 %0, tmp; }"
        : "=r"(addr) : "l"(smem_ptr));
    return addr;
}

#define CP_ASYNC16(dst_u32, src_ptr) \
    asm volatile("cp.async.cg.shared.global [%0], [%1], 16;" \
        :: "r"(dst_u32), "l"(__cvta_generic_to_global(src_ptr)))
#define CP_COMMIT() asm volatile("cp.async.commit_group;")
#define CP_WAIT1()  asm volatile("cp.async.wait_group 1;")

__device__ __forceinline__ void ldsm_x4(uint32_t* r, uint32_t addr) {
    asm volatile("ldmatrix.sync.aligned.m8n8.x4.shared.b16 {%0,%1,%2,%3}, [%4];"
        : "=r"(r[0]), "=r"(r[1]), "=r"(r[2]), "=r"(r[3]) : "r"(addr));
}

__device__ __forceinline__ void mma_bf16(float* d, const uint32_t* a, const uint32_t* b) {
    asm volatile(
        "mma.sync.aligned.m16n8k16.row.col.f32.bf16.bf16.f32 "
        "{%0,%1,%2,%3}, {%4,%5,%6,%7}, {%8,%9}, {%0,%1,%2,%3};"
        : "+f"(d[0]), "+f"(d[1]), "+f"(d[2]), "+f"(d[3])
        : "r"(a[0]), "r"(a[1]), "r"(a[2]), "r"(a[3]), "r"(b[0]), "r"(b[1]));
}

// ---------------------------------------------------------------------------
// fp32 -> bf16 hi/lo split (pre-pass; memory bound)
// ---------------------------------------------------------------------------
__global__ void split_kernel(const float* __restrict__ x,
                             __nv_bfloat16* __restrict__ hi,
                             __nv_bfloat16* __restrict__ lo, int n4)
{
    int i = blockIdx.x * blockDim.x + threadIdx.x;
    if (i >= n4) return;
    float4 v = ((const float4*)x)[i];
    __nv_bfloat16 h0 = __float2bfloat16(v.x);
    __nv_bfloat16 h1 = __float2bfloat16(v.y);
    __nv_bfloat16 h2 = __float2bfloat16(v.z);
    __nv_bfloat16 h3 = __float2bfloat16(v.w);
    __nv_bfloat16 l0 = __float2bfloat16(v.x - __bfloat162float(h0));
    __nv_bfloat16 l1 = __float2bfloat16(v.y - __bfloat162float(h1));
    __nv_bfloat16 l2 = __float2bfloat16(v.z - __bfloat162float(h2));
    __nv_bfloat16 l3 = __float2bfloat16(v.w - __bfloat162float(h3));
    __nv_bfloat162 hp0 = {h0, h1}, hp1 = {h2, h3};
    __nv_bfloat162 lp0 = {l0, l1}, lp1 = {l2, l3};
    ((__nv_bfloat162*)hi)[2 * i]     = hp0;
    ((__nv_bfloat162*)hi)[2 * i + 1] = hp1;
    ((__nv_bfloat162*)lo)[2 * i]     = lp0;
    ((__nv_bfloat162*)lo)[2 * i + 1] = lp1;
}

// ---------------------------------------------------------------------------
// Tensor-core GEMM NT via mma.sync (HMMA), bf16x3 compensated:
//   C[M,N] = (Ahi+Alo)[M,K] * (Bhi+Blo)[N,K]^T   ~ hi*hi + lo*hi + hi*lo
// 128x128 CTA tile, BK=32, 256 threads (8 warps, 2x4, 64x32 warp tiles),
// cp.async double buffer. Smem rows padded to 80B -> conflict-free ldmatrix.
// ---------------------------------------------------------------------------
#define GTILE 10240u                  // 128 rows * 80B
#define GSTAGE (4 * GTILE)            // Ahi, Alo, Bhi, Blo
#define GEMM_SMEM (2 * GSTAGE)        // 81920 B

__device__ __forceinline__ void gemm_load_stage(
    uint32_t sdst,
    const __nv_bfloat16* __restrict__ Ahi, const __nv_bfloat16* __restrict__ Alo,
    const __nv_bfloat16* __restrict__ Bhi, const __nv_bfloat16* __restrict__ Blo,
    int bm, int bn, int K, int k0, int tid)
{
#pragma unroll
    for (int i = 0; i < 2; ++i) {
        int idx = tid + i * 256;           // 0..511 -> (row, 16B-chunk)
        int r = idx >> 2, c = idx & 3;
        uint32_t so = (uint32_t)(r * 80 + c * 16);
        size_t ga = (size_t)(bm + r) * K + k0 + c * 8;
        size_t gb = (size_t)(bn + r) * K + k0 + c * 8;
        CP_ASYNC16(sdst + so,              Ahi + ga);
        CP_ASYNC16(sdst + GTILE + so,      Alo + ga);
        CP_ASYNC16(sdst + 2 * GTILE + so,  Bhi + gb);
        CP_ASYNC16(sdst + 3 * GTILE + so,  Blo + gb);
    }
}

__global__ void __launch_bounds__(256) gemm_mma_kernel(
    const __nv_bfloat16* __restrict__ Ahi, const __nv_bfloat16* __restrict__ Alo,
    const __nv_bfloat16* __restrict__ Bhi, const __nv_bfloat16* __restrict__ Blo,
    float* __restrict__ C, int N, int K)
{
    extern __shared__ char smem[];
    const uint32_t sb = smem_to_u32(smem);
    const int tid = threadIdx.x;
    const int lane = tid & 31, wid = tid >> 5;
    const int wr = wid >> 2, wc = wid & 3;          // warp grid 2x4
    const int bm = blockIdx.y * 128, bn = blockIdx.x * 128;

    float acc[4][4][4];
#pragma unroll
    for (int mi = 0; mi < 4; ++mi)
#pragma unroll
        for (int ni = 0; ni < 4; ++ni)
#pragma unroll
            for (int j = 0; j < 4; ++j) acc[mi][ni][j] = 0.f;

    const int nk = K >> 5;
    gemm_load_stage(sb, Ahi, Alo, Bhi, Blo, bm, bn, K, 0, tid);
    CP_COMMIT();
    gemm_load_stage(sb + GSTAGE, Ahi, Alo, Bhi, Blo, bm, bn, K, 32, tid);
    CP_COMMIT();

    for (int ks = 0; ks < nk; ++ks) {
        CP_WAIT1();
        __syncthreads();
        const uint32_t sA = sb + (uint32_t)(ks & 1) * GSTAGE;
        const uint32_t sB = sA + 2 * GTILE;

#pragma unroll
        for (int kk = 0; kk < 2; ++kk) {
            const uint32_t colo = (uint32_t)(kk * 32 + (lane >> 4) * 16);
            uint32_t ahi[4][4], alo[4][4], bhi[4][2], blo[4][2];
#pragma unroll
            for (int mi = 0; mi < 4; ++mi) {
                uint32_t ro = (uint32_t)(wr * 64 + mi * 16 + (lane & 15)) * 80 + colo;
                ldsm_x4(ahi[mi], sA + ro);
                ldsm_x4(alo[mi], sA + GTILE + ro);
            }
#pragma unroll
            for (int nj = 0; nj < 2; ++nj) {
                uint32_t ro = (uint32_t)(wc * 32 + nj * 16 + (lane & 15)) * 80 + colo;
                uint32_t t[4], u[4];
                ldsm_x4(t, sB + ro);
                ldsm_x4(u, sB + GTILE + ro);
                bhi[nj * 2][0] = t[0]; bhi[nj * 2][1] = t[2];
                bhi[nj * 2 + 1][0] = t[1]; bhi[nj * 2 + 1][1] = t[3];
                blo[nj * 2][0] = u[0]; blo[nj * 2][1] = u[2];
                blo[nj * 2 + 1][0] = u[1]; blo[nj * 2 + 1][1] = u[3];
            }
#pragma unroll
            for (int mi = 0; mi < 4; ++mi)
#pragma unroll
                for (int ni = 0; ni < 4; ++ni)
                    mma_bf16(acc[mi][ni], ahi[mi], bhi[ni]);
#pragma unroll
            for (int mi = 0; mi < 4; ++mi)
#pragma unroll
                for (int ni = 0; ni < 4; ++ni)
                    mma_bf16(acc[mi][ni], alo[mi], bhi[ni]);
#pragma unroll
            for (int mi = 0; mi < 4; ++mi)
#pragma unroll
                for (int ni = 0; ni < 4; ++ni)
                    mma_bf16(acc[mi][ni], ahi[mi], blo[ni]);
        }

        __syncthreads();
        if (ks + 2 < nk)
            gemm_load_stage(sb + (uint32_t)(ks & 1) * GSTAGE, Ahi, Alo, Bhi, Blo,
                            bm, bn, K, (ks + 2) * 32, tid);
        CP_COMMIT();
    }

    // epilogue: direct fragment stores (float2 per half-fragment)
#pragma unroll
    for (int mi = 0; mi < 4; ++mi) {
        int row = bm + wr * 64 + mi * 16 + (lane >> 2);
#pragma unroll
        for (int ni = 0; ni < 4; ++ni) {
            int col = bn + wc * 32 + ni * 8 + (lane & 3) * 2;
            float2 v0 = make_float2(acc[mi][ni][0], acc[mi][ni][1]);
            float2 v1 = make_float2(acc[mi][ni][2], acc[mi][ni][3]);
            *(float2*)&C[(size_t)row * N + col] = v0;
            *(float2*)&C[(size_t)(row + 8) * N + col] = v1;
        }
    }
}

// ---------------------------------------------------------------------------
// RoPE in-place on q and k thirds of qkv (B,T,3,H,D) layout.
// ---------------------------------------------------------------------------
__global__ void rope_kernel(float* __restrict__ qkv)
{
    int idx = blockIdx.x * blockDim.x + threadIdx.x;
    int i = idx & 31;
    int h = (idx >> 5) & 15;
    int t = (idx >> 9) & 2047;
    int b = idx >> 20;

    float p = powf(10000.0f, (float)(2 * i) * (1.0f / 64.0f));
    float ang = (float)t * (1.0f / p);
    float sn, cs;
    sincosf(ang, &sn, &cs);

    size_t base = ((size_t)(b * T_SEQ + t)) * QKV_COLS + h * D_HEAD;
    float q1 = qkv[base + i], q2 = qkv[base + i + 32];
    qkv[base + i]      =  q1 * cs + q2 * sn;
    qkv[base + i + 32] = -q1 * sn + q2 * cs;
    base += C_DIM;
    float k1 = qkv[base + i], k2 = qkv[base + i + 32];
    qkv[base + i]      =  k1 * cs + k2 * sn;
    qkv[base + i + 32] = -k1 * sn + k2 * cs;
}

// ---------------------------------------------------------------------------
// fp32 flash attention, causal. 1 thread = 1 query row; 128 queries/block.
// ---------------------------------------------------------------------------
__global__ void __launch_bounds__(128) flash_kernel(
    const float* __restrict__ qkv, float* __restrict__ y)
{
    __shared__ float4 Ks[16 * 16];
    __shared__ float4 Vs[16 * 16];

    const int tid = threadIdx.x;
    const int qtile = blockIdx.x;
    const int bh = blockIdx.y;
    const int b = bh >> 4;
    const int h = bh & 15;
    const int qpos = qtile * 128 + tid;

    const float* qptr = qkv + ((size_t)(b * T_SEQ + qpos)) * QKV_COLS + h * D_HEAD;
    float q[64];
#pragma unroll
    for (int dd = 0; dd < 16; ++dd) {
        float4 v = *(const float4*)(qptr + dd * 4);
        q[4 * dd + 0] = v.x * 0.125f;
        q[4 * dd + 1] = v.y * 0.125f;
        q[4 * dd + 2] = v.z * 0.125f;
        q[4 * dd + 3] = v.w * 0.125f;
    }

    float m = -1e30f, l = 0.f;
    float acc[64];
#pragma unroll
    for (int d = 0; d < 64; ++d) acc[d] = 0.f;

    const int ntiles = (qtile + 1) * 8;
    const int lrow = tid >> 3;
    const int lcol = (tid & 7) * 8;
    const float* kbaseptr = qkv + ((size_t)(b * T_SEQ)) * QKV_COLS + C_DIM + h * D_HEAD + lcol;
    const float* vbaseptr = kbaseptr + C_DIM;

    for (int kt = 0; kt < ntiles; ++kt) {
        const int kbase = kt * 16;
        {
            const float* kp = kbaseptr + (size_t)(kbase + lrow) * QKV_COLS;
            const float* vp = vbaseptr + (size_t)(kbase + lrow) * QKV_COLS;
            float4 k0 = *(const float4*)kp;
            float4 k1 = *(const float4*)(kp + 4);
            float4 v0 = *(const float4*)vp;
            float4 v1 = *(const float4*)(vp + 4);
            int so = lrow * 16 + (lcol >> 2);
            Ks[so] = k0; Ks[so + 1] = k1;
            Vs[so] = v0; Vs[so + 1] = v1;
        }
        __syncthreads();

        if (kbase <= qpos) {
            const bool full = (kbase + 15 <= qpos);
            float sc[16];
#pragma unroll
            for (int c = 0; c < 16; ++c) {
                float d0 = 0.f, d1 = 0.f, d2 = 0.f, d3 = 0.f;
#pragma unroll
                for (int dd = 0; dd < 16; ++dd) {
                    float4 kv = Ks[c * 16 + dd];
                    d0 = fmaf(q[4 * dd + 0], kv.x, d0);
                    d1 = fmaf(q[4 * dd + 1], kv.y, d1);
                    d2 = fmaf(q[4 * dd + 2], kv.z, d2);
                    d3 = fmaf(q[4 * dd + 3], kv.w, d3);
                }
                float sv = (d0 + d1) + (d2 + d3);
                sc[c] = (full || (kbase + c <= qpos)) ? sv : -1e30f;
            }
            float tm = sc[0];
#pragma unroll
            for (int c = 1; c < 16; ++c) tm = fmaxf(tm, sc[c]);
            float mnew = fmaxf(m, tm);
            float corr = __expf(m - mnew);
            l *= corr;
#pragma unroll
            for (int d = 0; d < 64; ++d) acc[d] *= corr;
#pragma unroll
            for (int c = 0; c < 16; ++c) {
                float pr = __expf(sc[c] - mnew);
                l += pr;
#pragma unroll
                for (int dd = 0; dd < 16; ++dd) {
                    float4 vv = Vs[c * 16 + dd];
                    acc[4 * dd + 0] = fmaf(pr, vv.x, acc[4 * dd + 0]);
                    acc[4 * dd + 1] = fmaf(pr, vv.y, acc[4 * dd + 1]);
                    acc[4 * dd + 2] = fmaf(pr, vv.z, acc[4 * dd + 2]);
                    acc[4 * dd + 3] = fmaf(pr, vv.w, acc[4 * dd + 3]);
                }
            }
            m = mnew;
        }
        __syncthreads();
    }

    const float invl = 1.0f / l;
    float* yp = y + ((size_t)(b * T_SEQ + qpos)) * C_DIM + h * D_HEAD;
#pragma unroll
    for (int dd = 0; dd < 16; ++dd) {
        float4 o = make_float4(acc[4 * dd + 0] * invl, acc[4 * dd + 1] * invl,
                               acc[4 * dd + 2] * invl, acc[4 * dd + 3] * invl);
        *(float4*)(yp + 4 * dd) = o;
    }
}

// ---------------------------------------------------------------------------
extern "C" void kernel_launch(void* const* d_in, const int* in_sizes, int n_in,
                              void* d_out, int out_size)
{
    const float* x      = (const float*)d_in[0];
    const float* w_attn = (const float*)d_in[1];
    const float* w_proj = (const float*)d_in[2];
    float* out = (float*)d_out;

    float *qkv, *y;
    __nv_bfloat16 *xhi, *xlo, *wahi, *walo, *wphi, *wplo, *yhi, *ylo;
    cudaGetSymbolAddress((void**)&qkv, g_qkv);
    cudaGetSymbolAddress((void**)&y, g_y);
    cudaGetSymbolAddress((void**)&xhi, g_xhi);
    cudaGetSymbolAddress((void**)&xlo, g_xlo);
    cudaGetSymbolAddress((void**)&wahi, g_wahi);
    cudaGetSymbolAddress((void**)&walo, g_walo);
    cudaGetSymbolAddress((void**)&wphi, g_wphi);
    cudaGetSymbolAddress((void**)&wplo, g_wplo);
    cudaGetSymbolAddress((void**)&yhi, g_yhi);
    cudaGetSymbolAddress((void**)&ylo, g_ylo);

    static bool attr_set = false;
    if (!attr_set) {
        cudaFuncSetAttribute(gemm_mma_kernel,
                             cudaFuncAttributeMaxDynamicSharedMemorySize, GEMM_SMEM);
        attr_set = true;
    }

    // splits of the GEMM inputs
    {
        int n4 = M_ROWS * C_DIM / 4;
        split_kernel<<<(n4 + 255) / 256, 256>>>(x, xhi, xlo, n4);
        n4 = QKV_COLS * C_DIM / 4;
        split_kernel<<<(n4 + 255) / 256, 256>>>(w_attn, wahi, walo, n4);
        n4 = C_DIM * C_DIM / 4;
        split_kernel<<<(n4 + 255) / 256, 256>>>(w_proj, wphi, wplo, n4);
    }
    // 1) qkv = x @ w_attn^T   (M=4096, N=3072, K=1024)  — HMMA bf16x3
    {
        dim3 grid(QKV_COLS / 128, M_ROWS / 128);
        gemm_mma_kernel<<<grid, 256, GEMM_SMEM>>>(xhi, xlo, wahi, walo, qkv,
                                                  QKV_COLS, C_DIM);
    }
    // 2) RoPE
    {
        int total = B_DIM * T_SEQ * H_DIM * 32;
        rope_kernel<<<total / 256, 256>>>(qkv);
    }
    // 3) flash attention -> y
    {
        dim3 grid(T_SEQ / 128, B_DIM * H_DIM);
        flash_kernel<<<grid, 128>>>(qkv, y);
    }
    // split y, then 4) out = y @ w_proj^T (M=4096, N=1024, K=1024) — HMMA bf16x3
    {
        int n4 = M_ROWS * C_DIM / 4;
        split_kernel<<<(n4 + 255) / 256, 256>>>(y, yhi, ylo, n4);
        dim3 grid(C_DIM / 128, M_ROWS / 128);
        gemm_mma_kernel<<<grid, 256, GEMM_SMEM>>>(yhi, ylo, wphi, wplo, out,
                                                  C_DIM, C_DIM);
    }
}

// round 4
// speedup vs baseline: 3.0216x; 2.2783x over previous
#include <cuda_runtime.h>
#include <cuda_bf16.h>
#include <cstdint>
#include <math.h>

#define B_DIM 2
#define T_SEQ 2048
#define C_DIM 1024
#define H_DIM 16
#define D_HEAD 64
#define M_ROWS (B_DIM * T_SEQ)       // 4096
#define QKV_COLS (3 * C_DIM)         // 3072

// ---------------------------------------------------------------------------
// Scratch (allocation-free rule: __device__ globals)
// ---------------------------------------------------------------------------
__device__ float g_qkv[(size_t)M_ROWS * QKV_COLS];   // (B,T,3,H,D)
__device__ float g_y[(size_t)M_ROWS * C_DIM];        // attention output

__device__ __nv_bfloat16 g_xhi[(size_t)M_ROWS * C_DIM];
__device__ __nv_bfloat16 g_xlo[(size_t)M_ROWS * C_DIM];
__device__ __nv_bfloat16 g_wahi[(size_t)QKV_COLS * C_DIM];
__device__ __nv_bfloat16 g_walo[(size_t)QKV_COLS * C_DIM];
__device__ __nv_bfloat16 g_wphi[(size_t)C_DIM * C_DIM];
__device__ __nv_bfloat16 g_wplo[(size_t)C_DIM * C_DIM];
__device__ __nv_bfloat16 g_yhi[(size_t)M_ROWS * C_DIM];
__device__ __nv_bfloat16 g_ylo[(size_t)M_ROWS * C_DIM];

// head-major bf16 hi/lo Q,K,V: (B,H,T,D)
#define HD_ELEMS ((size_t)B_DIM * H_DIM * T_SEQ * D_HEAD)
__device__ __nv_bfloat16 g_Qhi[HD_ELEMS];
__device__ __nv_bfloat16 g_Qlo[HD_ELEMS];
__device__ __nv_bfloat16 g_Khi[HD_ELEMS];
__device__ __nv_bfloat16 g_Klo[HD_ELEMS];
__device__ __nv_bfloat16 g_Vhi[HD_ELEMS];
__device__ __nv_bfloat16 g_Vlo[HD_ELEMS];

// ---------------------------------------------------------------------------
// helpers
// ---------------------------------------------------------------------------
__device__ __forceinline__ uint32_t smem_to_u32(const void* smem_ptr) {
    uint32_t addr;
    asm("{ .reg .u64 tmp; cvta.to.shared.u64 tmp, %1; cvt.u32.u64 %0, tmp; }"
        : "=r"(addr) : "l"(smem_ptr));
    return addr;
}

#define CP_ASYNC16(dst_u32, src_ptr) \
    asm volatile("cp.async.cg.shared.global [%0], [%1], 16;" \
        :: "r"(dst_u32), "l"(__cvta_generic_to_global(src_ptr)))
#define CP_COMMIT() asm volatile("cp.async.commit_group;")
#define CP_WAIT1()  asm volatile("cp.async.wait_group 1;")
#define CP_WAIT0()  asm volatile("cp.async.wait_group 0;")

__device__ __forceinline__ void ldsm_x4(uint32_t* r, uint32_t addr) {
    asm volatile("ldmatrix.sync.aligned.m8n8.x4.shared.b16 {%0,%1,%2,%3}, [%4];"
        : "=r"(r[0]), "=r"(r[1]), "=r"(r[2]), "=r"(r[3]) : "r"(addr));
}
__device__ __forceinline__ void ldsm_x4t(uint32_t* r, uint32_t addr) {
    asm volatile("ldmatrix.sync.aligned.m8n8.x4.trans.shared.b16 {%0,%1,%2,%3}, [%4];"
        : "=r"(r[0]), "=r"(r[1]), "=r"(r[2]), "=r"(r[3]) : "r"(addr));
}

__device__ __forceinline__ void mma_bf16(float* d, const uint32_t* a, const uint32_t* b) {
    asm volatile(
        "mma.sync.aligned.m16n8k16.row.col.f32.bf16.bf16.f32 "
        "{%0,%1,%2,%3}, {%4,%5,%6,%7}, {%8,%9}, {%0,%1,%2,%3};"
        : "+f"(d[0]), "+f"(d[1]), "+f"(d[2]), "+f"(d[3])
        : "r"(a[0]), "r"(a[1]), "r"(a[2]), "r"(a[3]), "r"(b[0]), "r"(b[1]));
}

__device__ __forceinline__ void pack_hl(float a, float b, uint32_t& hi, uint32_t& lo) {
    __nv_bfloat162 h = __floats2bfloat162_rn(a, b);
    float ra = a - __bfloat162float(h.x);
    float rb = b - __bfloat162float(h.y);
    __nv_bfloat162 l = __floats2bfloat162_rn(ra, rb);
    hi = *(uint32_t*)&h;
    lo = *(uint32_t*)&l;
}

// ---------------------------------------------------------------------------
// fp32 -> bf16 hi/lo split (pre-pass; memory bound)
// ---------------------------------------------------------------------------
__global__ void split_kernel(const float* __restrict__ x,
                             __nv_bfloat16* __restrict__ hi,
                             __nv_bfloat16* __restrict__ lo, int n4)
{
    int i = blockIdx.x * blockDim.x + threadIdx.x;
    if (i >= n4) return;
    float4 v = ((const float4*)x)[i];
    __nv_bfloat162 h0 = __floats2bfloat162_rn(v.x, v.y);
    __nv_bfloat162 h1 = __floats2bfloat162_rn(v.z, v.w);
    __nv_bfloat162 l0 = __floats2bfloat162_rn(v.x - __bfloat162float(h0.x),
                                              v.y - __bfloat162float(h0.y));
    __nv_bfloat162 l1 = __floats2bfloat162_rn(v.z - __bfloat162float(h1.x),
                                              v.w - __bfloat162float(h1.y));
    ((__nv_bfloat162*)hi)[2 * i]     = h0;
    ((__nv_bfloat162*)hi)[2 * i + 1] = h1;
    ((__nv_bfloat162*)lo)[2 * i]     = l0;
    ((__nv_bfloat162*)lo)[2 * i + 1] = l1;
}

// ---------------------------------------------------------------------------
// Tensor-core GEMM NT via mma.sync (HMMA), bf16x3 compensated (unchanged)
// ---------------------------------------------------------------------------
#define GTILE 10240u
#define GSTAGE (4 * GTILE)
#define GEMM_SMEM (2 * GSTAGE)

__device__ __forceinline__ void gemm_load_stage(
    uint32_t sdst,
    const __nv_bfloat16* __restrict__ Ahi, const __nv_bfloat16* __restrict__ Alo,
    const __nv_bfloat16* __restrict__ Bhi, const __nv_bfloat16* __restrict__ Blo,
    int bm, int bn, int K, int k0, int tid)
{
#pragma unroll
    for (int i = 0; i < 2; ++i) {
        int idx = tid + i * 256;
        int r = idx >> 2, c = idx & 3;
        uint32_t so = (uint32_t)(r * 80 + c * 16);
        size_t ga = (size_t)(bm + r) * K + k0 + c * 8;
        size_t gb = (size_t)(bn + r) * K + k0 + c * 8;
        CP_ASYNC16(sdst + so,              Ahi + ga);
        CP_ASYNC16(sdst + GTILE + so,      Alo + ga);
        CP_ASYNC16(sdst + 2 * GTILE + so,  Bhi + gb);
        CP_ASYNC16(sdst + 3 * GTILE + so,  Blo + gb);
    }
}

__global__ void __launch_bounds__(256) gemm_mma_kernel(
    const __nv_bfloat16* __restrict__ Ahi, const __nv_bfloat16* __restrict__ Alo,
    const __nv_bfloat16* __restrict__ Bhi, const __nv_bfloat16* __restrict__ Blo,
    float* __restrict__ C, int N, int K)
{
    extern __shared__ char smem[];
    const uint32_t sb = smem_to_u32(smem);
    const int tid = threadIdx.x;
    const int lane = tid & 31, wid = tid >> 5;
    const int wr = wid >> 2, wc = wid & 3;
    const int bm = blockIdx.y * 128, bn = blockIdx.x * 128;

    float acc[4][4][4];
#pragma unroll
    for (int mi = 0; mi < 4; ++mi)
#pragma unroll
        for (int ni = 0; ni < 4; ++ni)
#pragma unroll
            for (int j = 0; j < 4; ++j) acc[mi][ni][j] = 0.f;

    const int nk = K >> 5;
    gemm_load_stage(sb, Ahi, Alo, Bhi, Blo, bm, bn, K, 0, tid);
    CP_COMMIT();
    gemm_load_stage(sb + GSTAGE, Ahi, Alo, Bhi, Blo, bm, bn, K, 32, tid);
    CP_COMMIT();

    for (int ks = 0; ks < nk; ++ks) {
        CP_WAIT1();
        __syncthreads();
        const uint32_t sA = sb + (uint32_t)(ks & 1) * GSTAGE;
        const uint32_t sB = sA + 2 * GTILE;

#pragma unroll
        for (int kk = 0; kk < 2; ++kk) {
            const uint32_t colo = (uint32_t)(kk * 32 + (lane >> 4) * 16);
            uint32_t ahi[4][4], alo[4][4], bhi[4][2], blo[4][2];
#pragma unroll
            for (int mi = 0; mi < 4; ++mi) {
                uint32_t ro = (uint32_t)(wr * 64 + mi * 16 + (lane & 15)) * 80 + colo;
                ldsm_x4(ahi[mi], sA + ro);
                ldsm_x4(alo[mi], sA + GTILE + ro);
            }
#pragma unroll
            for (int nj = 0; nj < 2; ++nj) {
                uint32_t ro = (uint32_t)(wc * 32 + nj * 16 + (lane & 15)) * 80 + colo;
                uint32_t t[4], u[4];
                ldsm_x4(t, sB + ro);
                ldsm_x4(u, sB + GTILE + ro);
                bhi[nj * 2][0] = t[0]; bhi[nj * 2][1] = t[2];
                bhi[nj * 2 + 1][0] = t[1]; bhi[nj * 2 + 1][1] = t[3];
                blo[nj * 2][0] = u[0]; blo[nj * 2][1] = u[2];
                blo[nj * 2 + 1][0] = u[1]; blo[nj * 2 + 1][1] = u[3];
            }
#pragma unroll
            for (int mi = 0; mi < 4; ++mi)
#pragma unroll
                for (int ni = 0; ni < 4; ++ni)
                    mma_bf16(acc[mi][ni], ahi[mi], bhi[ni]);
#pragma unroll
            for (int mi = 0; mi < 4; ++mi)
#pragma unroll
                for (int ni = 0; ni < 4; ++ni)
                    mma_bf16(acc[mi][ni], alo[mi], bhi[ni]);
#pragma unroll
            for (int mi = 0; mi < 4; ++mi)
#pragma unroll
                for (int ni = 0; ni < 4; ++ni)
                    mma_bf16(acc[mi][ni], ahi[mi], blo[ni]);
        }

        __syncthreads();
        if (ks + 2 < nk)
            gemm_load_stage(sb + (uint32_t)(ks & 1) * GSTAGE, Ahi, Alo, Bhi, Blo,
                            bm, bn, K, (ks + 2) * 32, tid);
        CP_COMMIT();
    }

#pragma unroll
    for (int mi = 0; mi < 4; ++mi) {
        int row = bm + wr * 64 + mi * 16 + (lane >> 2);
#pragma unroll
        for (int ni = 0; ni < 4; ++ni) {
            int col = bn + wc * 32 + ni * 8 + (lane & 3) * 2;
            float2 v0 = make_float2(acc[mi][ni][0], acc[mi][ni][1]);
            float2 v1 = make_float2(acc[mi][ni][2], acc[mi][ni][3]);
            *(float2*)&C[(size_t)row * N + col] = v0;
            *(float2*)&C[(size_t)(row + 8) * N + col] = v1;
        }
    }
}

// ---------------------------------------------------------------------------
// Prep: RoPE (q,k) + fp32->bf16 hi/lo split + head-major relayout (B,H,T,D).
// Scale 1/8 folded into Q. One thread per (b,t,h, pair i in 0..31).
// ---------------------------------------------------------------------------
__global__ void rope_split_kernel(const float* __restrict__ qkv,
                                  __nv_bfloat16* __restrict__ Qhi, __nv_bfloat16* __restrict__ Qlo,
                                  __nv_bfloat16* __restrict__ Khi, __nv_bfloat16* __restrict__ Klo,
                                  __nv_bfloat16* __restrict__ Vhi, __nv_bfloat16* __restrict__ Vlo)
{
    int idx = blockIdx.x * blockDim.x + threadIdx.x;
    int i = idx & 31;
    int h = (idx >> 5) & 15;
    int t = (idx >> 9) & 2047;
    int b = idx >> 20;

    float p = powf(10000.0f, (float)(2 * i) * (1.0f / 64.0f));
    float ang = (float)t * (1.0f / p);
    float sn, cs;
    sincosf(ang, &sn, &cs);

    size_t src = ((size_t)(b * T_SEQ + t)) * QKV_COLS + h * D_HEAD;
    size_t dst = ((size_t)((b * H_DIM + h) * T_SEQ + t)) * D_HEAD;

    // q (fold 1/8 scale)
    {
        float q1 = qkv[src + i], q2 = qkv[src + i + 32];
        float a = (q1 * cs + q2 * sn) * 0.125f;
        float c2 = (-q1 * sn + q2 * cs) * 0.125f;
        __nv_bfloat16 ha = __float2bfloat16(a), hc = __float2bfloat16(c2);
        Qhi[dst + i] = ha; Qhi[dst + i + 32] = hc;
        Qlo[dst + i] = __float2bfloat16(a - __bfloat162float(ha));
        Qlo[dst + i + 32] = __float2bfloat16(c2 - __bfloat162float(hc));
    }
    // k
    {
        float k1 = qkv[src + C_DIM + i], k2 = qkv[src + C_DIM + i + 32];
        float a = k1 * cs + k2 * sn;
        float c2 = -k1 * sn + k2 * cs;
        __nv_bfloat16 ha = __float2bfloat16(a), hc = __float2bfloat16(c2);
        Khi[dst + i] = ha; Khi[dst + i + 32] = hc;
        Klo[dst + i] = __float2bfloat16(a - __bfloat162float(ha));
        Klo[dst + i + 32] = __float2bfloat16(c2 - __bfloat162float(hc));
    }
    // v (plain split)
    {
        float v1 = qkv[src + 2 * C_DIM + i], v2 = qkv[src + 2 * C_DIM + i + 32];
        __nv_bfloat16 ha = __float2bfloat16(v1), hc = __float2bfloat16(v2);
        Vhi[dst + i] = ha; Vhi[dst + i + 32] = hc;
        Vlo[dst + i] = __float2bfloat16(v1 - __bfloat162float(ha));
        Vlo[dst + i + 32] = __float2bfloat16(v2 - __bfloat162float(hc));
    }
}

// ---------------------------------------------------------------------------
// Flash attention via mma.sync, causal, bf16 hi/lo 3-pass.
// CTA: 128 queries x one (b,h); 8 warps x 16 rows. 64-key tiles, double buffer.
// ---------------------------------------------------------------------------
#define FPITCH 144u
#define FTILE  (64u * FPITCH)          // 9216
#define FSTAGE (4u * FTILE)            // Khi, Klo, Vhi, Vlo = 36864
#define FL_SMEM (2u * FSTAGE)          // 73728

__device__ __forceinline__ void flash_load_stage(
    uint32_t dstbase, int kb,
    const __nv_bfloat16* __restrict__ Kh, const __nv_bfloat16* __restrict__ Kl,
    const __nv_bfloat16* __restrict__ Vh, const __nv_bfloat16* __restrict__ Vl,
    int tid)
{
#pragma unroll
    for (int j = 0; j < 2; ++j) {
        int idx = tid + j * 256;               // 0..511
        int tile = idx >> 7;                   // 0..3
        int r = (idx >> 1) & 63;
        int c = (idx & 1) * 4;                 // 2 x 64B? no: 8 chunks/row -> redo
        (void)tile; (void)r; (void)c;
    }
    // 2048 16B-chunks: 4 tiles * 64 rows * 8 chunks
#pragma unroll
    for (int j = 0; j < 8; ++j) {
        int idx = tid + j * 256;
        int tile = idx >> 9;                   // 0..3
        int r = (idx >> 3) & 63;
        int c = idx & 7;
        uint32_t dst = dstbase + (uint32_t)tile * FTILE + (uint32_t)r * FPITCH + c * 16;
        const __nv_bfloat16* src =
            (tile == 0 ? Kh : tile == 1 ? Kl : tile == 2 ? Vh : Vl);
        CP_ASYNC16(dst, src + (size_t)(kb + r) * D_HEAD + c * 8);
    }
}

__global__ void __launch_bounds__(256) flash_mma_kernel(
    const __nv_bfloat16* __restrict__ Qhi, const __nv_bfloat16* __restrict__ Qlo,
    const __nv_bfloat16* __restrict__ Khi, const __nv_bfloat16* __restrict__ Klo,
    const __nv_bfloat16* __restrict__ Vhi, const __nv_bfloat16* __restrict__ Vlo,
    float* __restrict__ y)
{
    extern __shared__ char fsm[];
    const uint32_t sb = smem_to_u32(fsm);
    const int tid = threadIdx.x;
    const int lane = tid & 31, w = tid >> 5;
    const int qt = gridDim.x - 1 - blockIdx.x;     // heavy tiles first
    const int bh = blockIdx.y;
    const int qb = qt * 128;

    const size_t hoff = (size_t)bh * T_SEQ * D_HEAD;
    const __nv_bfloat16* Qh = Qhi + hoff + (size_t)qb * D_HEAD;
    const __nv_bfloat16* Ql = Qlo + hoff + (size_t)qb * D_HEAD;
    const __nv_bfloat16* Kh = Khi + hoff;
    const __nv_bfloat16* Kl = Klo + hoff;
    const __nv_bfloat16* Vh = Vhi + hoff;
    const __nv_bfloat16* Vl = Vlo + hoff;

    // ---- stage Q (hi at sb, lo at sb+128*FPITCH) and extract A fragments ----
#pragma unroll
    for (int j = 0; j < 8; ++j) {
        int idx = tid + j * 256;               // 2048 chunks
        int tile = idx >> 10;
        int r = (idx >> 3) & 127;
        int c = idx & 7;
        uint32_t dst = sb + (uint32_t)tile * (128u * FPITCH) + (uint32_t)r * FPITCH + c * 16;
        const __nv_bfloat16* src = (tile == 0 ? Qh : Ql);
        CP_ASYNC16(dst, src + (size_t)r * D_HEAD + c * 8);
    }
    CP_COMMIT();
    CP_WAIT0();
    __syncthreads();

    uint32_t qhf[4][4], qlf[4][4];
    {
        uint32_t arow = (uint32_t)(w * 16 + (lane & 7) + ((lane & 8) ? 8 : 0));
        uint32_t acol = (uint32_t)(((lane & 16) ? 16 : 0));
#pragma unroll
        for (int kk = 0; kk < 4; ++kk) {
            uint32_t a = sb + arow * FPITCH + kk * 32 + acol;
            ldsm_x4(qhf[kk], a);
            ldsm_x4(qlf[kk], a + 128u * FPITCH);
        }
    }
    __syncthreads();   // Q fragments extracted; smem reusable

    float o[8][4];
#pragma unroll
    for (int j = 0; j < 8; ++j)
#pragma unroll
        for (int c = 0; c < 4; ++c) o[j][c] = 0.f;
    float m0 = -1e30f, m1 = -1e30f, l0 = 0.f, l1 = 0.f;

    const int ntiles = 2 * qt + 2;
    const int wqmin = qb + w * 16;
    const int wqmax = wqmin + 15;

    flash_load_stage(sb, 0, Kh, Kl, Vh, Vl, tid);
    CP_COMMIT();
    flash_load_stage(sb + FSTAGE, 64, Kh, Kl, Vh, Vl, tid);
    CP_COMMIT();

    for (int kt = 0; kt < ntiles; ++kt) {
        CP_WAIT1();
        __syncthreads();
        const uint32_t stage = sb + (uint32_t)(kt & 1) * FSTAGE;
        const int kb = kt * 64;

        if (kb <= wqmax) {
            // ---- S = Q K^T (3-pass hi/lo) ----
            float s[8][4];
#pragma unroll
            for (int j = 0; j < 8; ++j)
#pragma unroll
                for (int c = 0; c < 4; ++c) s[j][c] = 0.f;

            const uint32_t br = (uint32_t)((lane & 7) + ((lane & 16) ? 8 : 0));
            const uint32_t bc = (uint32_t)((lane & 8) ? 16 : 0);
#pragma unroll
            for (int kg = 0; kg < 4; ++kg) {
                uint32_t rowa = (uint32_t)(kg * 16) + br;
#pragma unroll
                for (int kk = 0; kk < 4; ++kk) {
                    uint32_t addr = stage + rowa * FPITCH + kk * 32 + bc;
                    uint32_t kh4[4], kl4[4];
                    ldsm_x4(kh4, addr);
                    ldsm_x4(kl4, addr + FTILE);
                    mma_bf16(s[2 * kg],     qhf[kk], &kh4[0]);
                    mma_bf16(s[2 * kg + 1], qhf[kk], &kh4[2]);
                    mma_bf16(s[2 * kg],     qlf[kk], &kh4[0]);
                    mma_bf16(s[2 * kg + 1], qlf[kk], &kh4[2]);
                    mma_bf16(s[2 * kg],     qhf[kk], &kl4[0]);
                    mma_bf16(s[2 * kg + 1], qhf[kk], &kl4[2]);
                }
            }

            // ---- causal mask ----
            if (kb + 63 > wqmin) {
                int r0 = wqmin + (lane >> 2), r1 = r0 + 8;
#pragma unroll
                for (int j = 0; j < 8; ++j) {
                    int k0 = kb + j * 8 + ((lane & 3) << 1);
                    if (k0 > r0)     s[j][0] = -1e30f;
                    if (k0 + 1 > r0) s[j][1] = -1e30f;
                    if (k0 > r1)     s[j][2] = -1e30f;
                    if (k0 + 1 > r1) s[j][3] = -1e30f;
                }
            }

            // ---- online softmax ----
            float mx0 = -1e30f, mx1 = -1e30f;
#pragma unroll
            for (int j = 0; j < 8; ++j) {
                mx0 = fmaxf(mx0, fmaxf(s[j][0], s[j][1]));
                mx1 = fmaxf(mx1, fmaxf(s[j][2], s[j][3]));
            }
            mx0 = fmaxf(mx0, __shfl_xor_sync(0xffffffffu, mx0, 1));
            mx0 = fmaxf(mx0, __shfl_xor_sync(0xffffffffu, mx0, 2));
            mx1 = fmaxf(mx1, __shfl_xor_sync(0xffffffffu, mx1, 1));
            mx1 = fmaxf(mx1, __shfl_xor_sync(0xffffffffu, mx1, 2));
            float m0n = fmaxf(m0, mx0), m1n = fmaxf(m1, mx1);
            float sc0 = __expf(m0 - m0n), sc1 = __expf(m1 - m1n);
            float rs0 = 0.f, rs1 = 0.f;
#pragma unroll
            for (int j = 0; j < 8; ++j) {
                s[j][0] = __expf(s[j][0] - m0n);
                s[j][1] = __expf(s[j][1] - m0n);
                s[j][2] = __expf(s[j][2] - m1n);
                s[j][3] = __expf(s[j][3] - m1n);
                rs0 += s[j][0] + s[j][1];
                rs1 += s[j][2] + s[j][3];
            }
            rs0 += __shfl_xor_sync(0xffffffffu, rs0, 1);
            rs0 += __shfl_xor_sync(0xffffffffu, rs0, 2);
            rs1 += __shfl_xor_sync(0xffffffffu, rs1, 1);
            rs1 += __shfl_xor_sync(0xffffffffu, rs1, 2);
            l0 = l0 * sc0 + rs0;
            l1 = l1 * sc1 + rs1;
            m0 = m0n; m1 = m1n;
#pragma unroll
            for (int j = 0; j < 8; ++j) {
                o[j][0] *= sc0; o[j][1] *= sc0;
                o[j][2] *= sc1; o[j][3] *= sc1;
            }

            // ---- pack P hi/lo A-fragments ----
            uint32_t aph[4][4], apl[4][4];
#pragma unroll
            for (int kk2 = 0; kk2 < 4; ++kk2) {
                int j0 = 2 * kk2, j1 = j0 + 1;
                pack_hl(s[j0][0], s[j0][1], aph[kk2][0], apl[kk2][0]);
                pack_hl(s[j0][2], s[j0][3], aph[kk2][1], apl[kk2][1]);
                pack_hl(s[j1][0], s[j1][1], aph[kk2][2], apl[kk2][2]);
                pack_hl(s[j1][2], s[j1][3], aph[kk2][3], apl[kk2][3]);
            }

            // ---- O += P V (3-pass) via ldmatrix.trans on V ----
            const uint32_t vr = (uint32_t)((lane & 7) + ((lane & 8) ? 8 : 0));
            const uint32_t vc = (uint32_t)((lane & 16) ? 16 : 0);
#pragma unroll
            for (int dg = 0; dg < 4; ++dg) {
#pragma unroll
                for (int kk2 = 0; kk2 < 4; ++kk2) {
                    uint32_t addr = stage + 2 * FTILE +
                                    (uint32_t)(kk2 * 16 + vr) * FPITCH + dg * 32 + vc;
                    uint32_t vh4[4], vl4[4];
                    ldsm_x4t(vh4, addr);
                    ldsm_x4t(vl4, addr + FTILE);
                    mma_bf16(o[2 * dg],     aph[kk2], &vh4[0]);
                    mma_bf16(o[2 * dg + 1], aph[kk2], &vh4[2]);
                    mma_bf16(o[2 * dg],     apl[kk2], &vh4[0]);
                    mma_bf16(o[2 * dg + 1], apl[kk2], &vh4[2]);
                    mma_bf16(o[2 * dg],     aph[kk2], &vl4[0]);
                    mma_bf16(o[2 * dg + 1], aph[kk2], &vl4[2]);
                }
            }
        }

        __syncthreads();
        if (kt + 2 < ntiles)
            flash_load_stage(sb + (uint32_t)(kt & 1) * FSTAGE, (kt + 2) * 64,
                             Kh, Kl, Vh, Vl, tid);
        CP_COMMIT();
    }

    // ---- normalize and write ----
    const float inv0 = 1.0f / l0, inv1 = 1.0f / l1;
    const int b = bh >> 4, h = bh & 15;
    const int r0 = qb + w * 16 + (lane >> 2);
#pragma unroll
    for (int j = 0; j < 8; ++j) {
        int col = h * 64 + j * 8 + (lane & 3) * 2;
        float2 v0 = make_float2(o[j][0] * inv0, o[j][1] * inv0);
        float2 v1 = make_float2(o[j][2] * inv1, o[j][3] * inv1);
        *(float2*)&y[(size_t)(b * T_SEQ + r0) * C_DIM + col] = v0;
        *(float2*)&y[(size_t)(b * T_SEQ + r0 + 8) * C_DIM + col] = v1;
    }
}

// ---------------------------------------------------------------------------
extern "C" void kernel_launch(void* const* d_in, const int* in_sizes, int n_in,
                              void* d_out, int out_size)
{
    const float* x      = (const float*)d_in[0];
    const float* w_attn = (const float*)d_in[1];
    const float* w_proj = (const float*)d_in[2];
    float* out = (float*)d_out;

    float *qkv, *y;
    __nv_bfloat16 *xhi, *xlo, *wahi, *walo, *wphi, *wplo, *yhi, *ylo;
    __nv_bfloat16 *Qhi, *Qlo, *Khi, *Klo, *Vhi, *Vlo;
    cudaGetSymbolAddress((void**)&qkv, g_qkv);
    cudaGetSymbolAddress((void**)&y, g_y);
    cudaGetSymbolAddress((void**)&xhi, g_xhi);
    cudaGetSymbolAddress((void**)&xlo, g_xlo);
    cudaGetSymbolAddress((void**)&wahi, g_wahi);
    cudaGetSymbolAddress((void**)&walo, g_walo);
    cudaGetSymbolAddress((void**)&wphi, g_wphi);
    cudaGetSymbolAddress((void**)&wplo, g_wplo);
    cudaGetSymbolAddress((void**)&yhi, g_yhi);
    cudaGetSymbolAddress((void**)&ylo, g_ylo);
    cudaGetSymbolAddress((void**)&Qhi, g_Qhi);
    cudaGetSymbolAddress((void**)&Qlo, g_Qlo);
    cudaGetSymbolAddress((void**)&Khi, g_Khi);
    cudaGetSymbolAddress((void**)&Klo, g_Klo);
    cudaGetSymbolAddress((void**)&Vhi, g_Vhi);
    cudaGetSymbolAddress((void**)&Vlo, g_Vlo);

    static bool attr_set = false;
    if (!attr_set) {
        cudaFuncSetAttribute(gemm_mma_kernel,
                             cudaFuncAttributeMaxDynamicSharedMemorySize, GEMM_SMEM);
        cudaFuncSetAttribute(flash_mma_kernel,
                             cudaFuncAttributeMaxDynamicSharedMemorySize, FL_SMEM);
        attr_set = true;
    }

    // input splits
    {
        int n4 = M_ROWS * C_DIM / 4;
        split_kernel<<<(n4 + 255) / 256, 256>>>(x, xhi, xlo, n4);
        n4 = QKV_COLS * C_DIM / 4;
        split_kernel<<<(n4 + 255) / 256, 256>>>(w_attn, wahi, walo, n4);
        n4 = C_DIM * C_DIM / 4;
        split_kernel<<<(n4 + 255) / 256, 256>>>(w_proj, wphi, wplo, n4);
    }
    // 1) qkv = x @ w_attn^T
    {
        dim3 grid(QKV_COLS / 128, M_ROWS / 128);
        gemm_mma_kernel<<<grid, 256, GEMM_SMEM>>>(xhi, xlo, wahi, walo, qkv,
                                                  QKV_COLS, C_DIM);
    }
    // 2) RoPE + split + relayout
    {
        int total = B_DIM * T_SEQ * H_DIM * 32;
        rope_split_kernel<<<total / 256, 256>>>(qkv, Qhi, Qlo, Khi, Klo, Vhi, Vlo);
    }
    // 3) flash attention (tensor cores) -> y
    {
        dim3 grid(T_SEQ / 128, B_DIM * H_DIM);
        flash_mma_kernel<<<grid, 256, FL_SMEM>>>(Qhi, Qlo, Khi, Klo, Vhi, Vlo, y);
    }
    // 4) out = y @ w_proj^T
    {
        int n4 = M_ROWS * C_DIM / 4;
        split_kernel<<<(n4 + 255) / 256, 256>>>(y, yhi, ylo, n4);
        dim3 grid(C_DIM / 128, M_ROWS / 128);
        gemm_mma_kernel<<<grid, 256, GEMM_SMEM>>>(yhi, ylo, wphi, wplo, out,
                                                  C_DIM, C_DIM);
    }
}